// round 1
// baseline (speedup 1.0000x reference)
#include <cuda_runtime.h>
#include <cuda_bf16.h>
#include <cstddef>

// Problem constants
#define NH   6
#define NB   512
#define ND   2048
#define NC   1000
#define TAUC 0.5f

// Scratch (device globals — no allocation allowed)
__device__ float g_logits[NH * NB * NC];   // [6,512,1000] fp32
__device__ float g_lse   [NH * NB];
__device__ float g_conf  [NH * NB];
__device__ int   g_argmax[NH * NB];
__device__ int   g_exit  [NB];

// ---------------------------------------------------------------------------
// Kernel 1: batched fp32 GEMM  logits[h] = feats[h] @ W[h] + bias[h]
//   A = feats[h] : [512, 2048] row-major
//   B = W[h]     : [2048, 1000] row-major
// Tile: BM=128, BN=128, BK=8, 256 threads, 8x8 per thread.
// ---------------------------------------------------------------------------
#define BM 128
#define BN 128
#define BK 8
#define TM 8
#define TN 8

__global__ __launch_bounds__(256) void sdn_gemm_kernel(
    const float* __restrict__ feats,
    const float* __restrict__ W,
    const float* __restrict__ bias)
{
    const int h     = blockIdx.z;
    const int mTile = blockIdx.y;   // 0..3
    const int nTile = blockIdx.x;   // 0..7

    const float* A  = feats + (size_t)h * NB * ND;
    const float* Bm = W     + (size_t)h * ND * NC;

    __shared__ float As[BK][BM];
    __shared__ float Bs[BK][BN];

    const int tid = threadIdx.x;          // 0..255
    const int tx  = tid & 15;             // n direction
    const int ty  = tid >> 4;             // m direction

    const int m0 = mTile * BM;
    const int n0 = nTile * BN;

    // A loads: 128 rows x 8 cols = 256 float4 (one per thread)
    const int aRow = tid >> 1;            // 0..127
    const int aCol = (tid & 1) * 4;       // 0 or 4
    // B loads: 8 rows x 128 cols = 256 float4
    const int bRow = tid >> 5;            // 0..7
    const int bCol = (tid & 31) * 4;      // 0..124

    float acc[TM][TN];
    #pragma unroll
    for (int i = 0; i < TM; i++)
        #pragma unroll
        for (int j = 0; j < TN; j++) acc[i][j] = 0.0f;

    for (int k0 = 0; k0 < ND; k0 += BK) {
        // Load A tile (transpose into As[k][m])
        float4 av = *reinterpret_cast<const float4*>(
            A + (size_t)(m0 + aRow) * ND + k0 + aCol);
        As[aCol + 0][aRow] = av.x;
        As[aCol + 1][aRow] = av.y;
        As[aCol + 2][aRow] = av.z;
        As[aCol + 3][aRow] = av.w;

        // Load B tile (guard C=1000 edge; cols are multiples of 4, 1000%4==0)
        const int gcol = n0 + bCol;
        float4 bv = make_float4(0.f, 0.f, 0.f, 0.f);
        if (gcol < NC)
            bv = *reinterpret_cast<const float4*>(
                Bm + (size_t)(k0 + bRow) * NC + gcol);
        *reinterpret_cast<float4*>(&Bs[bRow][bCol]) = bv;

        __syncthreads();

        #pragma unroll
        for (int kk = 0; kk < BK; kk++) {
            float ar[TM], br[TN];
            float4 a0 = *reinterpret_cast<const float4*>(&As[kk][ty * TM]);
            float4 a1 = *reinterpret_cast<const float4*>(&As[kk][ty * TM + 4]);
            ar[0]=a0.x; ar[1]=a0.y; ar[2]=a0.z; ar[3]=a0.w;
            ar[4]=a1.x; ar[5]=a1.y; ar[6]=a1.z; ar[7]=a1.w;
            float4 b0 = *reinterpret_cast<const float4*>(&Bs[kk][tx * TN]);
            float4 b1 = *reinterpret_cast<const float4*>(&Bs[kk][tx * TN + 4]);
            br[0]=b0.x; br[1]=b0.y; br[2]=b0.z; br[3]=b0.w;
            br[4]=b1.x; br[5]=b1.y; br[6]=b1.z; br[7]=b1.w;
            #pragma unroll
            for (int i = 0; i < TM; i++)
                #pragma unroll
                for (int j = 0; j < TN; j++)
                    acc[i][j] = fmaf(ar[i], br[j], acc[i][j]);
        }
        __syncthreads();
    }

    // Epilogue: add bias, store to scratch logits
    #pragma unroll
    for (int i = 0; i < TM; i++) {
        const int m = m0 + ty * TM + i;
        #pragma unroll
        for (int j = 0; j < TN; j++) {
            const int n = n0 + tx * TN + j;
            if (n < NC) {
                g_logits[(size_t)h * NB * NC + (size_t)m * NC + n] =
                    acc[i][j] + bias[h * NC + n];
            }
        }
    }
}

// ---------------------------------------------------------------------------
// Kernel 2: per-row (h,b) stats over C=1000: max, argmax, logsumexp, conf
// One block (128 threads) per row.
// ---------------------------------------------------------------------------
__global__ __launch_bounds__(128) void sdn_rowstats_kernel()
{
    const int row = blockIdx.x;           // 0 .. 6*512-1
    const float* p = g_logits + (size_t)row * NC;
    const int tid = threadIdx.x;

    float vmax = -1e30f;
    int   vidx = 0;
    for (int c = tid; c < NC; c += 128) {
        float v = p[c];
        if (v > vmax) { vmax = v; vidx = c; }
    }

    __shared__ float smax[128];
    __shared__ int   sidx[128];
    smax[tid] = vmax; sidx[tid] = vidx;
    __syncthreads();
    for (int s = 64; s > 0; s >>= 1) {
        if (tid < s) {
            float ov = smax[tid + s]; int oi = sidx[tid + s];
            if (ov > smax[tid] || (ov == smax[tid] && oi < sidx[tid])) {
                smax[tid] = ov; sidx[tid] = oi;
            }
        }
        __syncthreads();
    }
    const float rmax = smax[0];

    float sum = 0.0f;
    for (int c = tid; c < NC; c += 128) sum += expf(p[c] - rmax);

    __shared__ float ssum[128];
    ssum[tid] = sum;
    __syncthreads();
    for (int s = 64; s > 0; s >>= 1) {
        if (tid < s) ssum[tid] += ssum[tid + s];
        __syncthreads();
    }

    if (tid == 0) {
        float lse = rmax + logf(ssum[0]);
        g_lse[row]    = lse;
        g_conf[row]   = expf(rmax - lse);   // max softmax prob
        g_argmax[row] = sidx[0];
    }
}

// ---------------------------------------------------------------------------
// Kernel 3: routing + loss + acc (single block, 512 threads, deterministic)
// ---------------------------------------------------------------------------
__global__ __launch_bounds__(512) void sdn_route_kernel(
    const int* __restrict__ y_true, float* __restrict__ out)
{
    const int b = threadIdx.x;   // one thread per sample

    int   firstExit = -1;
    float bestc = -1e30f;
    int   besth = 0;
    #pragma unroll
    for (int h = 0; h < NH; h++) {
        float c = g_conf[h * NB + b];
        if (firstExit < 0 && c >= TAUC) firstExit = h;
        if (c > bestc) { bestc = c; besth = h; }   // strict > == first argmax
    }
    const int ex = (firstExit >= 0) ? firstExit : besth;
    g_exit[b] = ex;

    const int y = y_true[b];
    const size_t rowbase = ((size_t)ex * NB + b);
    const float logit_y = g_logits[rowbase * NC + y];
    const float loss_b  = -(logit_y - g_lse[rowbase]);
    const float acc_b   = (g_argmax[rowbase] == y) ? 1.0f : 0.0f;

    out[NB * NC + b] = (float)ex;   // exit_idx as float

    __shared__ float sl[512];
    __shared__ float sa[512];
    sl[b] = loss_b; sa[b] = acc_b;
    __syncthreads();
    for (int s = 256; s > 0; s >>= 1) {
        if (b < s) { sl[b] += sl[b + s]; sa[b] += sa[b + s]; }
        __syncthreads();
    }
    if (b == 0) {
        out[NB * NC + NB + 0] = sl[0] / (float)NB;  // loss (mean)
        out[NB * NC + NB + 1] = sa[0] / (float)NB;  // acc (mean)
    }
}

// ---------------------------------------------------------------------------
// Kernel 4: gather routed outputs — out[b, :] = logits[exit[b], b, :]
// ---------------------------------------------------------------------------
__global__ __launch_bounds__(256) void sdn_gather_kernel(float* __restrict__ out)
{
    const int b  = blockIdx.x;
    const int ex = g_exit[b];
    const float4* src = reinterpret_cast<const float4*>(
        g_logits + ((size_t)ex * NB + b) * NC);
    float4* dst = reinterpret_cast<float4*>(out + (size_t)b * NC);
    for (int i = threadIdx.x; i < NC / 4; i += blockDim.x)
        dst[i] = src[i];
}

// ---------------------------------------------------------------------------
extern "C" void kernel_launch(void* const* d_in, const int* in_sizes, int n_in,
                              void* d_out, int out_size)
{
    const float* feats = (const float*)d_in[0];  // [6,512,2048]
    const float* W     = (const float*)d_in[1];  // [6,2048,1000]
    const float* bias  = (const float*)d_in[2];  // [6,1000]
    const int*   y     = (const int*)  d_in[3];  // [512]
    float* out = (float*)d_out;                  // 512514 floats

    dim3 grid((NC + BN - 1) / BN, NB / BM, NH);  // (8, 4, 6)
    sdn_gemm_kernel<<<grid, 256>>>(feats, W, bias);
    sdn_rowstats_kernel<<<NH * NB, 128>>>();
    sdn_route_kernel<<<1, 512>>>(y, out);
    sdn_gather_kernel<<<NB, 256>>>(out);
}

// round 6
// speedup vs baseline: 1.5126x; 1.5126x over previous
#include <cuda_runtime.h>
#include <cuda_bf16.h>
#include <cstdint>
#include <cstddef>

// ---------------------------------------------------------------------------
// Problem constants
// ---------------------------------------------------------------------------
#define GH 6
#define GM 512          // batch
#define GN 1000         // classes
#define GNP 1024        // padded classes
#define GK 2048         // feature dim
#define TAUC 0.5f

// GEMM tiling (mma.sync path)
#define BM 64
#define BN 128
#define BK 32                     // bf16 elems per stage (64 B rows)
#define NKB (GK / BK)             // 64 stages
#define A_TILE_B (BM * 64)        // 4096 B per A split tile
#define B_TILE_B (BN * 64)        // 8192 B per B split tile
#define STAGE_B (3 * A_TILE_B + 3 * B_TILE_B)   // 36864 B
#define SMEM_DYN (2 * STAGE_B + 1024)

// ---------------------------------------------------------------------------
// Device-global scratch (no allocation allowed)
// ---------------------------------------------------------------------------
__device__ __align__(16) __nv_bfloat16 g_fa0[GH * GM * GK];
__device__ __align__(16) __nv_bfloat16 g_fa1[GH * GM * GK];
__device__ __align__(16) __nv_bfloat16 g_fa2[GH * GM * GK];
__device__ __align__(16) __nv_bfloat16 g_wt0[GH * GNP * GK];
__device__ __align__(16) __nv_bfloat16 g_wt1[GH * GNP * GK];
__device__ __align__(16) __nv_bfloat16 g_wt2[GH * GNP * GK];
__device__ float g_logits[GH * GM * GN];
__device__ float g_lse   [GH * GM];
__device__ float g_conf  [GH * GM];
__device__ int   g_amax  [GH * GM];
__device__ int   g_exit  [GM];

// ---------------------------------------------------------------------------
// Helpers (baseline PTX only — safe on plain sm_103 target)
// ---------------------------------------------------------------------------
__device__ __forceinline__ uint32_t smem_to_u32(const void* p) {
    uint32_t a;
    asm("{ .reg .u64 t; cvta.to.shared.u64 t, %1; cvt.u32.u64 %0, t; }"
        : "=r"(a) : "l"(p));
    return a;
}

__device__ __forceinline__ void cp16(uint32_t s, const void* g) {
    asm volatile("cp.async.cg.shared.global [%0], [%1], 16;\n" :: "r"(s), "l"(g));
}
#define CP_COMMIT() asm volatile("cp.async.commit_group;\n" ::: "memory")
#define CP_WAIT1()  asm volatile("cp.async.wait_group 1;\n" ::: "memory")
#define CP_WAIT0()  asm volatile("cp.async.wait_group 0;\n" ::: "memory")

__device__ __forceinline__ void ldmx4(uint32_t* r, uint32_t addr) {
    asm volatile("ldmatrix.sync.aligned.m8n8.x4.shared.b16 {%0,%1,%2,%3}, [%4];"
                 : "=r"(r[0]), "=r"(r[1]), "=r"(r[2]), "=r"(r[3]) : "r"(addr));
}

__device__ __forceinline__ void mma16816(float* c, const uint32_t* a, const uint32_t* b) {
    asm volatile(
        "mma.sync.aligned.m16n8k16.row.col.f32.bf16.bf16.f32 "
        "{%0,%1,%2,%3}, {%4,%5,%6,%7}, {%8,%9}, {%0,%1,%2,%3};"
        : "+f"(c[0]), "+f"(c[1]), "+f"(c[2]), "+f"(c[3])
        : "r"(a[0]), "r"(a[1]), "r"(a[2]), "r"(a[3]), "r"(b[0]), "r"(b[1]));
}

// swizzled byte offset within a tile: 64B rows, 16B chunks, XOR with (row>>1)&3
__device__ __forceinline__ uint32_t swz(int row, int ch) {
    return (uint32_t)(row * 64 + ((ch ^ ((row >> 1) & 3)) << 4));
}

// ---------------------------------------------------------------------------
// Kernel A: convert feats fp32 -> 3 bf16 splits
// ---------------------------------------------------------------------------
__device__ __forceinline__ void split3(float v, __nv_bfloat16& s0,
                                       __nv_bfloat16& s1, __nv_bfloat16& s2) {
    s0 = __float2bfloat16_rn(v);
    float r = v - __bfloat162float(s0);
    s1 = __float2bfloat16_rn(r);
    float r2 = r - __bfloat162float(s1);
    s2 = __float2bfloat16_rn(r2);
}

__global__ __launch_bounds__(256) void convert_feats_kernel(const float* __restrict__ feats)
{
    const int gid = blockIdx.x * 256 + threadIdx.x;   // one per 4 elems
    float4 v = reinterpret_cast<const float4*>(feats)[gid];
    __nv_bfloat16 a0[4], a1[4], a2[4];
    split3(v.x, a0[0], a1[0], a2[0]);
    split3(v.y, a0[1], a1[1], a2[1]);
    split3(v.z, a0[2], a1[2], a2[2]);
    split3(v.w, a0[3], a1[3], a2[3]);
    reinterpret_cast<uint2*>(g_fa0)[gid] = *reinterpret_cast<uint2*>(a0);
    reinterpret_cast<uint2*>(g_fa1)[gid] = *reinterpret_cast<uint2*>(a1);
    reinterpret_cast<uint2*>(g_fa2)[gid] = *reinterpret_cast<uint2*>(a2);
}

// ---------------------------------------------------------------------------
// Kernel B: transpose + convert W [h,2048,1000] fp32 -> Wt [h,1024,2048] bf16 x3
// ---------------------------------------------------------------------------
__global__ __launch_bounds__(256) void convert_w_kernel(const float* __restrict__ W)
{
    const int h  = blockIdx.z;
    const int k0 = blockIdx.y * 32;
    const int c0 = blockIdx.x * 32;
    __shared__ float t[32][33];
    const int tx = threadIdx.x & 31;
    const int ty = threadIdx.x >> 5;   // 0..7

    #pragma unroll
    for (int i = 0; i < 4; i++) {
        int r = ty + i * 8;                 // local k
        int c = c0 + tx;
        t[r][tx] = (c < GN) ? W[((size_t)h * GK + (k0 + r)) * GN + c] : 0.0f;
    }
    __syncthreads();

    #pragma unroll
    for (int i = 0; i < 4; i++) {
        int rr = ty + i * 8;                // local c
        int cg = c0 + rr;
        int kg = k0 + tx;
        float v = t[tx][rr];
        __nv_bfloat16 s0, s1, s2;
        split3(v, s0, s1, s2);
        size_t idx = ((size_t)h * GNP + cg) * GK + kg;
        g_wt0[idx] = s0; g_wt1[idx] = s1; g_wt2[idx] = s2;
    }
}

// ---------------------------------------------------------------------------
// Kernel C: mma.sync bf16 GEMM (6-product fp32 emulation) + bias epilogue
//   C[h, m0:m0+64, n0:n0+128] = sum_splits feats_splits @ Wt_splits + bias
// ---------------------------------------------------------------------------
__device__ __forceinline__ void load_stage(
    uint32_t sb, int kb, int tid,
    const __nv_bfloat16* const* srcs)
{
    // A tiles (0..2): 256 chunks each; B tiles (3..5): 512 chunks each
    #pragma unroll
    for (int i = 0; i < 3; i++) {
        const int row = tid >> 2;
        const int ch  = tid & 3;
        const __nv_bfloat16* g = srcs[i] + (size_t)row * GK + kb * BK + ch * 8;
        cp16(sb + i * A_TILE_B + swz(row, ch), g);
    }
    #pragma unroll
    for (int j = 0; j < 6; j++) {
        const int t   = j >> 1;             // B tile 0..2
        const int w   = (j & 1) * 256 + tid;
        const int row = w >> 2;
        const int ch  = w & 3;
        const __nv_bfloat16* g = srcs[3 + t] + (size_t)row * GK + kb * BK + ch * 8;
        cp16(sb + 3 * A_TILE_B + t * B_TILE_B + swz(row, ch), g);
    }
}

__global__ __launch_bounds__(256, 2) void sdn_mma_gemm(const float* __restrict__ bias)
{
    extern __shared__ char smem[];
    const uint32_t sm0 = (smem_to_u32(smem) + 1023u) & ~1023u;

    const int tid  = threadIdx.x;
    const int wid  = tid >> 5;
    const int lane = tid & 31;
    const int wm   = (wid & 1) * 32;        // 2 warps along m
    const int wn   = (wid >> 1) * 32;       // 4 warps along n

    const int h  = blockIdx.z;
    const int m0 = blockIdx.y * BM;
    const int n0 = blockIdx.x * BN;

    const __nv_bfloat16* srcs[6] = {
        g_fa0 + ((size_t)h * GM  + m0) * GK,
        g_fa1 + ((size_t)h * GM  + m0) * GK,
        g_fa2 + ((size_t)h * GM  + m0) * GK,
        g_wt0 + ((size_t)h * GNP + n0) * GK,
        g_wt1 + ((size_t)h * GNP + n0) * GK,
        g_wt2 + ((size_t)h * GNP + n0) * GK
    };

    float acc[2][4][4];
    #pragma unroll
    for (int f = 0; f < 2; f++)
        #pragma unroll
        for (int n = 0; n < 4; n++)
            #pragma unroll
            for (int e = 0; e < 4; e++) acc[f][n][e] = 0.0f;

    // Prologue
    load_stage(sm0, 0, tid, srcs);
    CP_COMMIT();

    #pragma unroll 1
    for (int kb = 0; kb < NKB; kb++) {
        const int cur = kb & 1;
        if (kb + 1 < NKB) {
            load_stage(sm0 + (cur ^ 1) * STAGE_B, kb + 1, tid, srcs);
            CP_COMMIT();
            CP_WAIT1();
        } else {
            CP_WAIT0();
        }
        __syncthreads();

        const uint32_t sb = sm0 + cur * STAGE_B;
        #pragma unroll
        for (int ks = 0; ks < 2; ks++) {
            // A fragments: 3 splits x 2 m16 frags
            uint32_t ra[3][2][4];
            #pragma unroll
            for (int s = 0; s < 3; s++)
                #pragma unroll
                for (int f = 0; f < 2; f++) {
                    int row = wm + f * 16 + (lane & 15);
                    int ch  = 2 * ks + (lane >> 4);
                    ldmx4(ra[s][f], sb + s * A_TILE_B + swz(row, ch));
                }
            // B fragments: 3 splits x 2 x (n16 per ldmatrix.x4 = two n8 frags)
            uint32_t rb[3][2][4];
            #pragma unroll
            for (int s = 0; s < 3; s++)
                #pragma unroll
                for (int g = 0; g < 2; g++) {
                    int row = wn + g * 16 + (lane & 7) + ((lane >> 4) << 3);
                    int ch  = 2 * ks + ((lane >> 3) & 1);
                    ldmx4(rb[s][g], sb + 3 * A_TILE_B + s * B_TILE_B + swz(row, ch));
                }
            // 6 split-products, all into the same accumulator
            const int PA[6] = {0, 0, 1, 1, 0, 2};
            const int PB[6] = {0, 1, 0, 1, 2, 0};
            #pragma unroll
            for (int p = 0; p < 6; p++)
                #pragma unroll
                for (int f = 0; f < 2; f++)
                    #pragma unroll
                    for (int g = 0; g < 2; g++)
                        #pragma unroll
                        for (int h2 = 0; h2 < 2; h2++)
                            mma16816(acc[f][g * 2 + h2],
                                     ra[PA[p]][f], &rb[PB[p]][g][h2 * 2]);
        }
        __syncthreads();
    }

    // Epilogue: add bias, store fp32 logits
    const int g8  = lane >> 2;
    const int tig = lane & 3;
    #pragma unroll
    for (int f = 0; f < 2; f++) {
        #pragma unroll
        for (int nf = 0; nf < 4; nf++) {
            const int mrow = m0 + wm + f * 16 + g8;
            const int ncol = n0 + wn + nf * 8 + tig * 2;
            float* o0 = g_logits + ((size_t)h * GM + mrow) * GN;
            float* o1 = g_logits + ((size_t)h * GM + mrow + 8) * GN;
            if (ncol < GN) {
                float bz = bias[h * GN + ncol];
                o0[ncol] = acc[f][nf][0] + bz;
                o1[ncol] = acc[f][nf][2] + bz;
            }
            if (ncol + 1 < GN) {
                float bz = bias[h * GN + ncol + 1];
                o0[ncol + 1] = acc[f][nf][1] + bz;
                o1[ncol + 1] = acc[f][nf][3] + bz;
            }
        }
    }
}

// ---------------------------------------------------------------------------
// Kernel D: per-row stats (max, argmax, logsumexp, conf)
// ---------------------------------------------------------------------------
__global__ __launch_bounds__(128) void sdn_rowstats_kernel()
{
    const int row = blockIdx.x;
    const float* p = g_logits + (size_t)row * GN;
    const int tid = threadIdx.x;

    float vmax = -1e30f;
    int   vidx = 0;
    for (int c = tid; c < GN; c += 128) {
        float v = p[c];
        if (v > vmax) { vmax = v; vidx = c; }
    }
    __shared__ float smax[128];
    __shared__ int   sidx[128];
    smax[tid] = vmax; sidx[tid] = vidx;
    __syncthreads();
    for (int s = 64; s > 0; s >>= 1) {
        if (tid < s) {
            float ov = smax[tid + s]; int oi = sidx[tid + s];
            if (ov > smax[tid] || (ov == smax[tid] && oi < sidx[tid])) {
                smax[tid] = ov; sidx[tid] = oi;
            }
        }
        __syncthreads();
    }
    const float rmax = smax[0];

    float sum = 0.0f;
    for (int c = tid; c < GN; c += 128) sum += expf(p[c] - rmax);
    __shared__ float ssum[128];
    ssum[tid] = sum;
    __syncthreads();
    for (int s = 64; s > 0; s >>= 1) {
        if (tid < s) ssum[tid] += ssum[tid + s];
        __syncthreads();
    }
    if (tid == 0) {
        float lse = rmax + logf(ssum[0]);
        g_lse[row]  = lse;
        g_conf[row] = expf(rmax - lse);
        g_amax[row] = sidx[0];
    }
}

// ---------------------------------------------------------------------------
// Kernel E: routing + loss + acc
// ---------------------------------------------------------------------------
__global__ __launch_bounds__(512) void sdn_route_kernel(
    const int* __restrict__ y_true, float* __restrict__ out)
{
    const int b = threadIdx.x;

    int   firstExit = -1;
    float bestc = -1e30f;
    int   besth = 0;
    #pragma unroll
    for (int h = 0; h < GH; h++) {
        float c = g_conf[h * GM + b];
        if (firstExit < 0 && c >= TAUC) firstExit = h;
        if (c > bestc) { bestc = c; besth = h; }
    }
    const int ex = (firstExit >= 0) ? firstExit : besth;
    g_exit[b] = ex;

    const int y = y_true[b];
    const size_t rowbase = ((size_t)ex * GM + b);
    const float logit_y = g_logits[rowbase * GN + y];
    const float loss_b  = -(logit_y - g_lse[rowbase]);
    const float acc_b   = (g_amax[rowbase] == y) ? 1.0f : 0.0f;

    out[GM * GN + b] = (float)ex;

    __shared__ float sl[512];
    __shared__ float sa[512];
    sl[b] = loss_b; sa[b] = acc_b;
    __syncthreads();
    for (int s = 256; s > 0; s >>= 1) {
        if (b < s) { sl[b] += sl[b + s]; sa[b] += sa[b + s]; }
        __syncthreads();
    }
    if (b == 0) {
        out[GM * GN + GM + 0] = sl[0] / (float)GM;
        out[GM * GN + GM + 1] = sa[0] / (float)GM;
    }
}

// ---------------------------------------------------------------------------
// Kernel F: gather routed outputs
// ---------------------------------------------------------------------------
__global__ __launch_bounds__(256) void sdn_gather_kernel(float* __restrict__ out)
{
    const int b  = blockIdx.x;
    const int ex = g_exit[b];
    const float4* src = reinterpret_cast<const float4*>(
        g_logits + ((size_t)ex * GM + b) * GN);
    float4* dst = reinterpret_cast<float4*>(out + (size_t)b * GN);
    for (int i = threadIdx.x; i < GN / 4; i += blockDim.x)
        dst[i] = src[i];
}

// ---------------------------------------------------------------------------
extern "C" void kernel_launch(void* const* d_in, const int* in_sizes, int n_in,
                              void* d_out, int out_size)
{
    const float* feats = (const float*)d_in[0];  // [6,512,2048]
    const float* W     = (const float*)d_in[1];  // [6,2048,1000]
    const float* bias  = (const float*)d_in[2];  // [6,1000]
    const int*   y     = (const int*)  d_in[3];  // [512]
    float* out = (float*)d_out;

    cudaFuncSetAttribute(sdn_mma_gemm, cudaFuncAttributeMaxDynamicSharedMemorySize, SMEM_DYN);

    convert_feats_kernel<<<(GH * GM * GK / 4) / 256, 256>>>(feats);
    convert_w_kernel<<<dim3(GNP / 32, GK / 32, GH), 256>>>(W);
    sdn_mma_gemm<<<dim3(GNP / BN, GM / BM, GH), 256, SMEM_DYN>>>(bias);
    sdn_rowstats_kernel<<<GH * GM, 128>>>();
    sdn_route_kernel<<<1, 512>>>(y, out);
    sdn_gather_kernel<<<GM, 256>>>(out);
}

// round 7
// speedup vs baseline: 3.2806x; 2.1688x over previous
#include <cuda_runtime.h>
#include <cuda_bf16.h>
#include <cstdint>
#include <cstddef>

// ---------------------------------------------------------------------------
// Problem constants
// ---------------------------------------------------------------------------
#define GH 6
#define GM 512          // batch
#define GN 1000         // classes
#define GNP 1024        // padded classes
#define GK 2048         // feature dim
#define TAUC 0.5f

// GEMM tiling (mma.sync path)
#define BM 64
#define BN 128
#define BK 64                     // bf16 elems per stage (128 B rows)
#define NKB (GK / BK)             // 32 stages
#define A_TILE_B (BM * 128)       // 8192 B per A split tile
#define B_TILE_B (BN * 128)       // 16384 B per B split tile
#define STAGE_B (2 * A_TILE_B + 2 * B_TILE_B)   // 49152 B
#define SMEM_DYN (2 * STAGE_B + 1024)

// ---------------------------------------------------------------------------
// Device-global scratch (no allocation allowed)
// ---------------------------------------------------------------------------
__device__ __align__(16) __nv_bfloat16 g_fa0[GH * GM * GK];
__device__ __align__(16) __nv_bfloat16 g_fa1[GH * GM * GK];
__device__ __align__(16) __nv_bfloat16 g_wt0[GH * GNP * GK];
__device__ __align__(16) __nv_bfloat16 g_wt1[GH * GNP * GK];
__device__ float g_logits[GH * GM * GN];
__device__ float g_lse   [GH * GM];
__device__ float g_conf  [GH * GM];
__device__ int   g_amax  [GH * GM];
__device__ int   g_exit  [GM];

// ---------------------------------------------------------------------------
// Helpers (baseline PTX only — safe on plain sm_103 target)
// ---------------------------------------------------------------------------
__device__ __forceinline__ uint32_t smem_to_u32(const void* p) {
    uint32_t a;
    asm("{ .reg .u64 t; cvta.to.shared.u64 t, %1; cvt.u32.u64 %0, t; }"
        : "=r"(a) : "l"(p));
    return a;
}

__device__ __forceinline__ void cp16(uint32_t s, const void* g) {
    asm volatile("cp.async.cg.shared.global [%0], [%1], 16;\n" :: "r"(s), "l"(g));
}
#define CP_COMMIT() asm volatile("cp.async.commit_group;\n" ::: "memory")
#define CP_WAIT1()  asm volatile("cp.async.wait_group 1;\n" ::: "memory")
#define CP_WAIT0()  asm volatile("cp.async.wait_group 0;\n" ::: "memory")

__device__ __forceinline__ void ldmx4(uint32_t* r, uint32_t addr) {
    asm volatile("ldmatrix.sync.aligned.m8n8.x4.shared.b16 {%0,%1,%2,%3}, [%4];"
                 : "=r"(r[0]), "=r"(r[1]), "=r"(r[2]), "=r"(r[3]) : "r"(addr));
}

__device__ __forceinline__ void mma16816(float* c, const uint32_t* a, const uint32_t* b) {
    asm volatile(
        "mma.sync.aligned.m16n8k16.row.col.f32.bf16.bf16.f32 "
        "{%0,%1,%2,%3}, {%4,%5,%6,%7}, {%8,%9}, {%0,%1,%2,%3};"
        : "+f"(c[0]), "+f"(c[1]), "+f"(c[2]), "+f"(c[3])
        : "r"(a[0]), "r"(a[1]), "r"(a[2]), "r"(a[3]), "r"(b[0]), "r"(b[1]));
}

// swizzled byte offset within a tile: 128B rows, 16B chunks, xor-8
__device__ __forceinline__ uint32_t swz(int row, int ch) {
    return (uint32_t)(row * 128 + ((ch ^ (row & 7)) << 4));
}

// ---------------------------------------------------------------------------
// Kernel A: convert feats fp32 -> 2 bf16 splits
// ---------------------------------------------------------------------------
__device__ __forceinline__ void split2(float v, __nv_bfloat16& s0, __nv_bfloat16& s1) {
    s0 = __float2bfloat16_rn(v);
    s1 = __float2bfloat16_rn(v - __bfloat162float(s0));
}

__global__ __launch_bounds__(256) void convert_feats_kernel(const float* __restrict__ feats)
{
    const int gid = blockIdx.x * 256 + threadIdx.x;   // one per 4 elems
    float4 v = reinterpret_cast<const float4*>(feats)[gid];
    __nv_bfloat16 a0[4], a1[4];
    split2(v.x, a0[0], a1[0]);
    split2(v.y, a0[1], a1[1]);
    split2(v.z, a0[2], a1[2]);
    split2(v.w, a0[3], a1[3]);
    reinterpret_cast<uint2*>(g_fa0)[gid] = *reinterpret_cast<uint2*>(a0);
    reinterpret_cast<uint2*>(g_fa1)[gid] = *reinterpret_cast<uint2*>(a1);
}

// ---------------------------------------------------------------------------
// Kernel B: transpose + convert W [h,2048,1000] fp32 -> Wt [h,1024,2048] bf16 x2
// ---------------------------------------------------------------------------
__global__ __launch_bounds__(256) void convert_w_kernel(const float* __restrict__ W)
{
    const int h  = blockIdx.z;
    const int k0 = blockIdx.y * 32;
    const int c0 = blockIdx.x * 32;
    __shared__ float t[32][33];
    const int tx = threadIdx.x & 31;
    const int ty = threadIdx.x >> 5;   // 0..7

    #pragma unroll
    for (int i = 0; i < 4; i++) {
        int r = ty + i * 8;                 // local k
        int c = c0 + tx;
        t[r][tx] = (c < GN) ? W[((size_t)h * GK + (k0 + r)) * GN + c] : 0.0f;
    }
    __syncthreads();

    #pragma unroll
    for (int i = 0; i < 4; i++) {
        int rr = ty + i * 8;                // local c
        int cg = c0 + rr;
        int kg = k0 + tx;
        float v = t[tx][rr];
        __nv_bfloat16 s0, s1;
        split2(v, s0, s1);
        size_t idx = ((size_t)h * GNP + cg) * GK + kg;
        g_wt0[idx] = s0; g_wt1[idx] = s1;
    }
}

// ---------------------------------------------------------------------------
// Kernel C: mma.sync bf16 GEMM (3-product fp32 emulation) + bias epilogue
// ---------------------------------------------------------------------------
__device__ __forceinline__ void load_stage(
    uint32_t sb, int kb, int tid,
    const __nv_bfloat16* const* srcs)
{
    // A tiles (0..1): 512 chunks each = 2 iters of 256
    #pragma unroll
    for (int i = 0; i < 2; i++)
        #pragma unroll
        for (int it = 0; it < 2; it++) {
            const int q   = it * 256 + tid;
            const int row = q >> 3;
            const int ch  = q & 7;
            const __nv_bfloat16* g = srcs[i] + (size_t)row * GK + kb * BK + ch * 8;
            cp16(sb + i * A_TILE_B + swz(row, ch), g);
        }
    // B tiles (2..3): 1024 chunks each = 4 iters of 256
    #pragma unroll
    for (int i = 0; i < 2; i++)
        #pragma unroll
        for (int it = 0; it < 4; it++) {
            const int q   = it * 256 + tid;
            const int row = q >> 3;
            const int ch  = q & 7;
            const __nv_bfloat16* g = srcs[2 + i] + (size_t)row * GK + kb * BK + ch * 8;
            cp16(sb + 2 * A_TILE_B + i * B_TILE_B + swz(row, ch), g);
        }
}

__global__ __launch_bounds__(256, 2) void sdn_mma_gemm(const float* __restrict__ bias)
{
    extern __shared__ char smem[];
    const uint32_t sm0 = (smem_to_u32(smem) + 1023u) & ~1023u;

    const int tid  = threadIdx.x;
    const int wid  = tid >> 5;
    const int lane = tid & 31;
    const int wm   = (wid & 1) * 32;        // 2 warps along m
    const int wn   = (wid >> 1) * 32;       // 4 warps along n

    const int h  = blockIdx.z;
    const int m0 = blockIdx.y * BM;
    const int n0 = blockIdx.x * BN;

    const __nv_bfloat16* srcs[4] = {
        g_fa0 + ((size_t)h * GM  + m0) * GK,
        g_fa1 + ((size_t)h * GM  + m0) * GK,
        g_wt0 + ((size_t)h * GNP + n0) * GK,
        g_wt1 + ((size_t)h * GNP + n0) * GK
    };

    float acc[2][4][4];
    #pragma unroll
    for (int f = 0; f < 2; f++)
        #pragma unroll
        for (int n = 0; n < 4; n++)
            #pragma unroll
            for (int e = 0; e < 4; e++) acc[f][n][e] = 0.0f;

    // Prologue
    load_stage(sm0, 0, tid, srcs);
    CP_COMMIT();

    #pragma unroll 1
    for (int kb = 0; kb < NKB; kb++) {
        const int cur = kb & 1;
        if (kb + 1 < NKB) {
            load_stage(sm0 + (cur ^ 1) * STAGE_B, kb + 1, tid, srcs);
            CP_COMMIT();
            CP_WAIT1();
        } else {
            CP_WAIT0();
        }
        __syncthreads();

        const uint32_t sb = sm0 + cur * STAGE_B;
        #pragma unroll
        for (int ks = 0; ks < 4; ks++) {
            // A fragments: 2 splits x 2 m16 frags
            uint32_t ra[2][2][4];
            #pragma unroll
            for (int s = 0; s < 2; s++)
                #pragma unroll
                for (int f = 0; f < 2; f++) {
                    int row = wm + f * 16 + (lane & 15);
                    int ch  = 2 * ks + (lane >> 4);
                    ldmx4(ra[s][f], sb + s * A_TILE_B + swz(row, ch));
                }
            // B fragments: 2 splits x 2 n16 frags
            uint32_t rb[2][2][4];
            #pragma unroll
            for (int s = 0; s < 2; s++)
                #pragma unroll
                for (int g = 0; g < 2; g++) {
                    int row = wn + g * 16 + (lane & 7) + ((lane >> 4) << 3);
                    int ch  = 2 * ks + ((lane >> 3) & 1);
                    ldmx4(rb[s][g], sb + 2 * A_TILE_B + s * B_TILE_B + swz(row, ch));
                }
            // 3 split-products: a0b0 + a0b1 + a1b0
            const int PA[3] = {0, 0, 1};
            const int PB[3] = {0, 1, 0};
            #pragma unroll
            for (int p = 0; p < 3; p++)
                #pragma unroll
                for (int f = 0; f < 2; f++)
                    #pragma unroll
                    for (int g = 0; g < 2; g++)
                        #pragma unroll
                        for (int h2 = 0; h2 < 2; h2++)
                            mma16816(acc[f][g * 2 + h2],
                                     ra[PA[p]][f], &rb[PB[p]][g][h2 * 2]);
        }
        __syncthreads();
    }

    // Epilogue: add bias, store fp32 logits
    const int g8  = lane >> 2;
    const int tig = lane & 3;
    #pragma unroll
    for (int f = 0; f < 2; f++) {
        #pragma unroll
        for (int nf = 0; nf < 4; nf++) {
            const int mrow = m0 + wm + f * 16 + g8;
            const int ncol = n0 + wn + nf * 8 + tig * 2;
            float* o0 = g_logits + ((size_t)h * GM + mrow) * GN;
            float* o1 = g_logits + ((size_t)h * GM + mrow + 8) * GN;
            if (ncol < GN) {
                float bz = bias[h * GN + ncol];
                o0[ncol] = acc[f][nf][0] + bz;
                o1[ncol] = acc[f][nf][2] + bz;
            }
            if (ncol + 1 < GN) {
                float bz = bias[h * GN + ncol + 1];
                o0[ncol + 1] = acc[f][nf][1] + bz;
                o1[ncol + 1] = acc[f][nf][3] + bz;
            }
        }
    }
}

// ---------------------------------------------------------------------------
// Kernel D: per-row stats (max, argmax, logsumexp, conf) — register-cached
// ---------------------------------------------------------------------------
__global__ __launch_bounds__(128) void sdn_rowstats_kernel()
{
    const int row = blockIdx.x;
    const float* p = g_logits + (size_t)row * GN;
    const int tid = threadIdx.x;

    float v[8];
    #pragma unroll
    for (int i = 0; i < 8; i++) {
        int c = tid + i * 128;
        v[i] = (c < GN) ? p[c] : -1e30f;
    }

    float vmax = -1e30f;
    int   vidx = 0;
    #pragma unroll
    for (int i = 0; i < 8; i++)
        if (v[i] > vmax) { vmax = v[i]; vidx = tid + i * 128; }

    __shared__ float smax[128];
    __shared__ int   sidx[128];
    smax[tid] = vmax; sidx[tid] = vidx;
    __syncthreads();
    for (int s = 64; s > 0; s >>= 1) {
        if (tid < s) {
            float ov = smax[tid + s]; int oi = sidx[tid + s];
            if (ov > smax[tid] || (ov == smax[tid] && oi < sidx[tid])) {
                smax[tid] = ov; sidx[tid] = oi;
            }
        }
        __syncthreads();
    }
    const float rmax = smax[0];

    float sum = 0.0f;
    #pragma unroll
    for (int i = 0; i < 8; i++)
        sum += expf(v[i] - rmax);   // padded lanes: exp(-huge)=0

    __shared__ float ssum[128];
    ssum[tid] = sum;
    __syncthreads();
    for (int s = 64; s > 0; s >>= 1) {
        if (tid < s) ssum[tid] += ssum[tid + s];
        __syncthreads();
    }
    if (tid == 0) {
        float lse = rmax + logf(ssum[0]);
        g_lse[row]  = lse;
        g_conf[row] = expf(rmax - lse);
        g_amax[row] = sidx[0];
    }
}

// ---------------------------------------------------------------------------
// Kernel E: routing + loss + acc
// ---------------------------------------------------------------------------
__global__ __launch_bounds__(512) void sdn_route_kernel(
    const int* __restrict__ y_true, float* __restrict__ out)
{
    const int b = threadIdx.x;

    int   firstExit = -1;
    float bestc = -1e30f;
    int   besth = 0;
    #pragma unroll
    for (int h = 0; h < GH; h++) {
        float c = g_conf[h * GM + b];
        if (firstExit < 0 && c >= TAUC) firstExit = h;
        if (c > bestc) { bestc = c; besth = h; }
    }
    const int ex = (firstExit >= 0) ? firstExit : besth;
    g_exit[b] = ex;

    const int y = y_true[b];
    const size_t rowbase = ((size_t)ex * GM + b);
    const float logit_y = g_logits[rowbase * GN + y];
    const float loss_b  = -(logit_y - g_lse[rowbase]);
    const float acc_b   = (g_amax[rowbase] == y) ? 1.0f : 0.0f;

    out[GM * GN + b] = (float)ex;

    __shared__ float sl[512];
    __shared__ float sa[512];
    sl[b] = loss_b; sa[b] = acc_b;
    __syncthreads();
    for (int s = 256; s > 0; s >>= 1) {
        if (b < s) { sl[b] += sl[b + s]; sa[b] += sa[b + s]; }
        __syncthreads();
    }
    if (b == 0) {
        out[GM * GN + GM + 0] = sl[0] / (float)GM;
        out[GM * GN + GM + 1] = sa[0] / (float)GM;
    }
}

// ---------------------------------------------------------------------------
// Kernel F: gather routed outputs
// ---------------------------------------------------------------------------
__global__ __launch_bounds__(256) void sdn_gather_kernel(float* __restrict__ out)
{
    const int b  = blockIdx.x;
    const int ex = g_exit[b];
    const float4* src = reinterpret_cast<const float4*>(
        g_logits + ((size_t)ex * GM + b) * GN);
    float4* dst = reinterpret_cast<float4*>(out + (size_t)b * GN);
    for (int i = threadIdx.x; i < GN / 4; i += blockDim.x)
        dst[i] = src[i];
}

// ---------------------------------------------------------------------------
extern "C" void kernel_launch(void* const* d_in, const int* in_sizes, int n_in,
                              void* d_out, int out_size)
{
    const float* feats = (const float*)d_in[0];  // [6,512,2048]
    const float* W     = (const float*)d_in[1];  // [6,2048,1000]
    const float* bias  = (const float*)d_in[2];  // [6,1000]
    const int*   y     = (const int*)  d_in[3];  // [512]
    float* out = (float*)d_out;

    cudaFuncSetAttribute(sdn_mma_gemm, cudaFuncAttributeMaxDynamicSharedMemorySize, SMEM_DYN);

    convert_feats_kernel<<<(GH * GM * GK / 4) / 256, 256>>>(feats);
    convert_w_kernel<<<dim3(GNP / 32, GK / 32, GH), 256>>>(W);
    sdn_mma_gemm<<<dim3(GNP / BN, GM / BM, GH), 256, SMEM_DYN>>>(bias);
    sdn_rowstats_kernel<<<GH * GM, 128>>>();
    sdn_route_kernel<<<1, 512>>>(y, out);
    sdn_gather_kernel<<<GM, 256>>>(out);
}